// round 10
// baseline (speedup 1.0000x reference)
#include <cuda_runtime.h>
#include <math_constants.h>
#include <cstdint>

// Problem constants
#define S_LEN   4096
#define D_MODEL 512
#define H_NUM   8
#define HD      64
#define LDQKV   1536      // 3*D_MODEL

// Q pre-scale: 1/sqrt(64) * log2(e)  (softmax runs in exp2 domain)
#define Q_PRESCALE 0.18033688011112042f

// Scratch (no cudaMalloc allowed)
__device__ float g_qkv[S_LEN * LDQKV];    // [4096,1536]  Q|K|V (tf32-rounded, Q pre-scaled)
__device__ float g_attn[S_LEN * D_MODEL]; // [4096,512]   attention output (head-merged)

// ---------------------------------------------------------------------------
// Helpers
// ---------------------------------------------------------------------------
__device__ __forceinline__ uint32_t f2tf32(float x) {
    uint32_t r;
    asm("cvt.rna.tf32.f32 %0, %1;" : "=r"(r) : "f"(x));
    return r;
}

__device__ __forceinline__ float ex2f(float x) {
    float y;
    asm("ex2.approx.ftz.f32 %0, %1;" : "=f"(y) : "f"(x));
    return y;
}

__device__ __forceinline__ void mma_tf32(float d[4], const uint32_t a[4],
                                         const uint32_t b[2], const float c[4]) {
    asm volatile(
        "mma.sync.aligned.m16n8k8.row.col.f32.tf32.tf32.f32 "
        "{%0,%1,%2,%3}, {%4,%5,%6,%7}, {%8,%9}, {%10,%11,%12,%13};"
        : "=f"(d[0]), "=f"(d[1]), "=f"(d[2]), "=f"(d[3])
        : "r"(a[0]), "r"(a[1]), "r"(a[2]), "r"(a[3]),
          "r"(b[0]), "r"(b[1]),
          "f"(c[0]), "f"(c[1]), "f"(c[2]), "f"(c[3]));
}

__device__ __forceinline__ void ldsm_x4(uint32_t& r0, uint32_t& r1,
                                        uint32_t& r2, uint32_t& r3, uint32_t addr) {
    asm volatile("ldmatrix.sync.aligned.m8n8.x4.shared.b16 {%0,%1,%2,%3}, [%4];"
                 : "=r"(r0), "=r"(r1), "=r"(r2), "=r"(r3) : "r"(addr));
}

__device__ __forceinline__ uint32_t smem_u32(const void* p) {
    uint32_t a;
    asm("{ .reg .u64 t; cvta.to.shared.u64 t, %1; cvt.u32.u64 %0, t; }"
        : "=r"(a) : "l"(p));
    return a;
}

// ---------------------------------------------------------------------------
// tf32 tensor-core GEMM: C[M,N] = A[M,K] @ B[N,K]^T + bias[N]
// qkv_round=1: epilogue scales Q columns (<512) by Q_PRESCALE and rounds all
// outputs to tf32 (rna) so the flash kernel stages K/V with raw copies.
// ---------------------------------------------------------------------------
#define GLD 36
#define GEMM_SMEM (2 * 2 * 128 * GLD * 4)   // 73728 bytes

__global__ void __launch_bounds__(256, 2) gemm_tf32_bias(
    const float* __restrict__ A, const float* __restrict__ B,
    const float* __restrict__ bias, float* __restrict__ C,
    int M, int N, int K, int qkv_round)
{
    extern __shared__ float sm[];
    float* As[2] = { sm,                 sm + 128 * GLD     };
    float* Bs[2] = { sm + 2 * 128 * GLD, sm + 3 * 128 * GLD };

    const int tid  = threadIdx.x;
    const int lane = tid & 31;
    const int wid  = tid >> 5;
    const int qc   = lane & 3;
    const int qg   = lane >> 2;
    const int wm   = (wid & 3) * 32;
    const int wn   = (wid >> 2) * 64;
    const int m0   = blockIdx.y * 128;
    const int n0   = blockIdx.x * 128;

    float acc[2][8][4];
#pragma unroll
    for (int mf = 0; mf < 2; mf++)
#pragma unroll
        for (int nf = 0; nf < 8; nf++)
#pragma unroll
            for (int j = 0; j < 4; j++) acc[mf][nf][j] = 0.0f;

    const int nt = K / 32;

    float4 pa[4], pb[4];
#pragma unroll
    for (int i = 0; i < 4; i++) {
        int f   = tid + i * 256;
        int row = f >> 3;
        int c4  = (f & 7) << 2;
        pa[i] = *(const float4*)(A + (size_t)(m0 + row) * K + c4);
        pb[i] = *(const float4*)(B + (size_t)(n0 + row) * K + c4);
    }
#pragma unroll
    for (int i = 0; i < 4; i++) {
        int f   = tid + i * 256;
        int row = f >> 3;
        int c4  = (f & 7) << 2;
        float* a = As[0] + row * GLD + c4;
        a[0] = __uint_as_float(f2tf32(pa[i].x));
        a[1] = __uint_as_float(f2tf32(pa[i].y));
        a[2] = __uint_as_float(f2tf32(pa[i].z));
        a[3] = __uint_as_float(f2tf32(pa[i].w));
        float* b = Bs[0] + row * GLD + c4;
        b[0] = __uint_as_float(f2tf32(pb[i].x));
        b[1] = __uint_as_float(f2tf32(pb[i].y));
        b[2] = __uint_as_float(f2tf32(pb[i].z));
        b[3] = __uint_as_float(f2tf32(pb[i].w));
    }
    __syncthreads();

    for (int t = 0; t < nt; t++) {
        const int cur = t & 1;
        if (t + 1 < nt) {
            int k0 = (t + 1) * 32;
#pragma unroll
            for (int i = 0; i < 4; i++) {
                int f   = tid + i * 256;
                int row = f >> 3;
                int c4  = (f & 7) << 2;
                pa[i] = *(const float4*)(A + (size_t)(m0 + row) * K + k0 + c4);
                pb[i] = *(const float4*)(B + (size_t)(n0 + row) * K + k0 + c4);
            }
        }

        const float* as = As[cur];
        const float* bs = Bs[cur];
#pragma unroll
        for (int kc = 0; kc < 4; kc++) {
            uint32_t bfr[8][2];
#pragma unroll
            for (int nf = 0; nf < 8; nf++) {
                const float* bp = bs + (wn + nf * 8 + qg) * GLD + kc * 8 + qc;
                bfr[nf][0] = __float_as_uint(bp[0]);
                bfr[nf][1] = __float_as_uint(bp[4]);
            }
#pragma unroll
            for (int mf = 0; mf < 2; mf++) {
                const float* ap = as + (wm + mf * 16 + qg) * GLD + kc * 8 + qc;
                uint32_t afr[4];
                afr[0] = __float_as_uint(ap[0]);
                afr[1] = __float_as_uint(ap[8 * GLD]);
                afr[2] = __float_as_uint(ap[4]);
                afr[3] = __float_as_uint(ap[8 * GLD + 4]);
#pragma unroll
                for (int nf = 0; nf < 8; nf++)
                    mma_tf32(acc[mf][nf], afr, bfr[nf], acc[mf][nf]);
            }
        }

        if (t + 1 < nt) {
            const int nxt = cur ^ 1;
#pragma unroll
            for (int i = 0; i < 4; i++) {
                int f   = tid + i * 256;
                int row = f >> 3;
                int c4  = (f & 7) << 2;
                float* a = As[nxt] + row * GLD + c4;
                a[0] = __uint_as_float(f2tf32(pa[i].x));
                a[1] = __uint_as_float(f2tf32(pa[i].y));
                a[2] = __uint_as_float(f2tf32(pa[i].z));
                a[3] = __uint_as_float(f2tf32(pa[i].w));
                float* b = Bs[nxt] + row * GLD + c4;
                b[0] = __uint_as_float(f2tf32(pb[i].x));
                b[1] = __uint_as_float(f2tf32(pb[i].y));
                b[2] = __uint_as_float(f2tf32(pb[i].z));
                b[3] = __uint_as_float(f2tf32(pb[i].w));
            }
            __syncthreads();
        }
    }

#pragma unroll
    for (int mf = 0; mf < 2; mf++) {
        int row0 = m0 + wm + mf * 16 + qg;
#pragma unroll
        for (int nf = 0; nf < 8; nf++) {
            int col = n0 + wn + nf * 8 + 2 * qc;
            float b0 = bias[col], b1 = bias[col + 1];
            float2 v0 = make_float2(acc[mf][nf][0] + b0, acc[mf][nf][1] + b1);
            float2 v1 = make_float2(acc[mf][nf][2] + b0, acc[mf][nf][3] + b1);
            if (qkv_round) {
                float sc = (col < D_MODEL) ? Q_PRESCALE : 1.0f;  // scale Q only
                v0.x = __uint_as_float(f2tf32(v0.x * sc));
                v0.y = __uint_as_float(f2tf32(v0.y * sc));
                v1.x = __uint_as_float(f2tf32(v1.x * sc));
                v1.y = __uint_as_float(f2tf32(v1.y * sc));
            }
            *(float2*)(C + (size_t)row0 * N + col)       = v0;
            *(float2*)(C + (size_t)(row0 + 8) * N + col) = v1;
        }
    }
}

// ---------------------------------------------------------------------------
// Flash attention, tf32 mma, Br=128 / Bc=64 / Hd=64.
// 256 threads = 8 warps x 16 q-rows: 4 warps/SMSP at 2 CTAs/SM (R5/R8 ran
// only 2/SMSP and sat 3x above their issue/crossbar floors on exposed
// latency -- more warps is the binding lever, not fewer instructions).
// - K B-frags and P A-frags via ldmatrix.x4; V scalar (conflict-free).
// - K/V double-buffered; tile t+1 staged between softmax and PV, one
//   __syncthreads per tile.
// - softmax in exp2 domain (log2e folded into Q pre-scale by the GEMM).
// ---------------------------------------------------------------------------
#define LDA 68
#define LDB 72
// Ks x2 + Vs x2 + Ps[128]: (2*64*68 + 2*64*72 + 128*68)*4 = 106496 B
#define FLASH_SMEM ((2 * 64 * LDA + 2 * 64 * LDB + 128 * LDA) * 4)

__global__ void __launch_bounds__(256, 2) flash_mma_kernel(
    const float* __restrict__ qkv, float* __restrict__ attn_out)
{
    extern __shared__ float sm[];
    float* Ksb[2] = { sm,                sm + 64 * LDA };
    float* Vsb[2] = { sm + 2 * 64 * LDA, sm + 2 * 64 * LDA + 64 * LDB };
    float* Ps = sm + 2 * 64 * LDA + 2 * 64 * LDB;   // [128][LDA] (Q staging, then P)

    const int tid  = threadIdx.x;
    const int lane = tid & 31;
    const int wid  = tid >> 5;        // 0..7
    const int qc   = lane & 3;
    const int qg   = lane >> 2;
    const int h    = blockIdx.y;
    const int q0   = blockIdx.x * 128;
    const int colb = h * HD;
    const int wbase = wid * 16;       // 16 q-rows per warp

    // ldmatrix per-lane address components (mappings verified on HW in R6/R8)
    const int g  = lane >> 3;          // address group 0..3
    const int l7 = lane & 7;
    // K B-frag x4 (one x4 covers an nt pair at one kc)
    const uint32_t k_lane_off = (uint32_t)((((g & 2) << 2) + l7) * LDA * 4 + ((g & 1) << 4));
    const uint32_t ks_addr[2] = { smem_u32(Ksb[0]) + k_lane_off,
                                  smem_u32(Ksb[1]) + k_lane_off };
    // P A-frag x4 (one x4 = full m16k8 A fragment for this warp's rows)
    const uint32_t p_lane_off = (uint32_t)(((((g & 1) << 3) + l7) + wbase) * LDA * 4 + ((g >> 1) << 4));
    const uint32_t ps_addr = smem_u32(Ps) + p_lane_off;

    // staging coordinates: 256 threads cover a 64x64 tile in 4 row-steps
    const int srow = tid >> 4;          // 0..15
    const int sc4  = (tid & 15) << 2;   // 0..60

    // ---- Stage Q tile (pre-scaled, pre-rounded): raw copy into Ps ----
#pragma unroll
    for (int i = 0; i < 8; i++) {
        int f   = tid + i * 256;        // 0..2047 float4 idx
        int row = f >> 4;
        int c4  = (f & 15) << 2;
        *(float4*)(Ps + row * LDA + c4) =
            *(const float4*)(qkv + (size_t)(q0 + row) * LDQKV + colb + c4);
    }
    // ---- Stage KV tile 0 into buf 0 ----
    {
        const float* kb = qkv + (size_t)srow * LDQKV + colb + D_MODEL + sc4;
#pragma unroll
        for (int r = 0; r < 4; r++)
            *(float4*)(Ksb[0] + (srow + r * 16) * LDA + sc4) =
                *(const float4*)(kb + (size_t)(r * 16) * LDQKV);
#pragma unroll
        for (int r = 0; r < 4; r++)
            *(float4*)(Vsb[0] + (srow + r * 16) * LDB + sc4) =
                *(const float4*)(kb + (size_t)(r * 16) * LDQKV + D_MODEL);
    }
    __syncthreads();

    // ---- Q fragments to registers: 8 k-chunks (rows are warp-private,
    //      so no barrier needed before P later overwrites them) ----
    uint32_t qf[8][4];
    {
        const int r0 = wbase + qg;
#pragma unroll
        for (int kc = 0; kc < 8; kc++) {
            int d0 = kc * 8;
            qf[kc][0] = __float_as_uint(Ps[r0 * LDA + d0 + qc]);
            qf[kc][1] = __float_as_uint(Ps[(r0 + 8) * LDA + d0 + qc]);
            qf[kc][2] = __float_as_uint(Ps[r0 * LDA + d0 + qc + 4]);
            qf[kc][3] = __float_as_uint(Ps[(r0 + 8) * LDA + d0 + qc + 4]);
        }
    }

    float o[8][4];
#pragma unroll
    for (int nt = 0; nt < 8; nt++)
#pragma unroll
        for (int j = 0; j < 4; j++) o[nt][j] = 0.0f;
    float m_lo = -CUDART_INF_F, m_hi = -CUDART_INF_F;
    float l_lo = 0.0f, l_hi = 0.0f;

    const int NT = S_LEN / 64;
    for (int t = 0; t < NT; t++) {
        const int buf = t & 1;
        const uint32_t kaddr = ks_addr[buf];
        const float*   Vs    = Vsb[buf];

        // ---- S = Q K^T (K B-frags via LDSM, one x4 per nt-pair per kc) ----
        float s[8][4];
#pragma unroll
        for (int nt = 0; nt < 8; nt++)
#pragma unroll
            for (int j = 0; j < 4; j++) s[nt][j] = 0.0f;

#pragma unroll
        for (int kc = 0; kc < 8; kc++) {
#pragma unroll
            for (int ntp = 0; ntp < 4; ntp++) {
                uint32_t be[2], bo[2];
                ldsm_x4(be[0], be[1], bo[0], bo[1],
                        kaddr + (uint32_t)(ntp * 16 * LDA * 4 + kc * 32));
                mma_tf32(s[2 * ntp],     qf[kc], be, s[2 * ntp]);
                mma_tf32(s[2 * ntp + 1], qf[kc], bo, s[2 * ntp + 1]);
            }
        }

        // ---- Online softmax (exp2 domain), store P ----
        {
            const int r0 = wbase + qg;
            const int r1 = r0 + 8;

            float mlo = -CUDART_INF_F, mhi = -CUDART_INF_F;
#pragma unroll
            for (int nt = 0; nt < 8; nt++) {
                mlo = fmaxf(mlo, fmaxf(s[nt][0], s[nt][1]));
                mhi = fmaxf(mhi, fmaxf(s[nt][2], s[nt][3]));
            }
            mlo = fmaxf(mlo, __shfl_xor_sync(0xffffffffu, mlo, 1));
            mlo = fmaxf(mlo, __shfl_xor_sync(0xffffffffu, mlo, 2));
            mhi = fmaxf(mhi, __shfl_xor_sync(0xffffffffu, mhi, 1));
            mhi = fmaxf(mhi, __shfl_xor_sync(0xffffffffu, mhi, 2));

            float mnlo = fmaxf(m_lo, mlo);
            float mnhi = fmaxf(m_hi, mhi);
            float alo  = ex2f(m_lo - mnlo);   // 0 on first tile
            float ahi  = ex2f(m_hi - mnhi);
            m_lo = mnlo; m_hi = mnhi;

            float tlo = 0.0f, thi = 0.0f;
#pragma unroll
            for (int nt = 0; nt < 8; nt++) {
                float p0 = ex2f(s[nt][0] - mnlo);
                float p1 = ex2f(s[nt][1] - mnlo);
                float p2 = ex2f(s[nt][2] - mnhi);
                float p3 = ex2f(s[nt][3] - mnhi);
                tlo += p0 + p1;
                thi += p2 + p3;
                uint2 plo = make_uint2(f2tf32(p0), f2tf32(p1));
                uint2 phi = make_uint2(f2tf32(p2), f2tf32(p3));
                *(uint2*)(Ps + r0 * LDA + nt * 8 + 2 * qc) = plo;
                *(uint2*)(Ps + r1 * LDA + nt * 8 + 2 * qc) = phi;
            }
            tlo += __shfl_xor_sync(0xffffffffu, tlo, 1);
            tlo += __shfl_xor_sync(0xffffffffu, tlo, 2);
            thi += __shfl_xor_sync(0xffffffffu, thi, 1);
            thi += __shfl_xor_sync(0xffffffffu, thi, 2);
            l_lo = l_lo * alo + tlo;
            l_hi = l_hi * ahi + thi;

#pragma unroll
            for (int nt = 0; nt < 8; nt++) {
                o[nt][0] *= alo; o[nt][1] *= alo;
                o[nt][2] *= ahi; o[nt][3] *= ahi;
            }
        }

        __syncwarp();   // P rows warp-private: order STS before LDSM

        // ---- Stage KV tile t+1 into buf^1 (latency hidden behind PV) ----
        if (t + 1 < NT) {
            const float* kb = qkv + (size_t)((t + 1) * 64 + srow) * LDQKV
                            + colb + D_MODEL + sc4;
            float* Kn = Ksb[buf ^ 1];
            float* Vn = Vsb[buf ^ 1];
#pragma unroll
            for (int r = 0; r < 4; r++)
                *(float4*)(Kn + (srow + r * 16) * LDA + sc4) =
                    *(const float4*)(kb + (size_t)(r * 16) * LDQKV);
#pragma unroll
            for (int r = 0; r < 4; r++)
                *(float4*)(Vn + (srow + r * 16) * LDB + sc4) =
                    *(const float4*)(kb + (size_t)(r * 16) * LDQKV + D_MODEL);
        }

        // ---- O += P V  (P A-frags via LDSM; V scalar, conflict-free) ----
#pragma unroll
        for (int kc = 0; kc < 8; kc++) {
            uint32_t a[4];
            ldsm_x4(a[0], a[1], a[2], a[3], ps_addr + (uint32_t)(kc * 32));
#pragma unroll
            for (int nt = 0; nt < 8; nt++) {
                uint32_t b[2];
                b[0] = __float_as_uint(Vs[(kc * 8 + qc) * LDB + nt * 8 + qg]);
                b[1] = __float_as_uint(Vs[(kc * 8 + qc + 4) * LDB + nt * 8 + qg]);
                mma_tf32(o[nt], a, b, o[nt]);
            }
        }
        __syncthreads();   // buf reads + buf^1 staging writes complete
    }

    // ---- Epilogue ----
    {
        const int r0 = wbase + qg;
        const int r1 = r0 + 8;
        float ilo = 1.0f / l_lo;
        float ihi = 1.0f / l_hi;
#pragma unroll
        for (int nt = 0; nt < 8; nt++) {
            float2 vlo = make_float2(o[nt][0] * ilo, o[nt][1] * ilo);
            float2 vhi = make_float2(o[nt][2] * ihi, o[nt][3] * ihi);
            *(float2*)(attn_out + (size_t)(q0 + r0) * D_MODEL + colb + nt * 8 + 2 * qc) = vlo;
            *(float2*)(attn_out + (size_t)(q0 + r1) * D_MODEL + colb + nt * 8 + 2 * qc) = vhi;
        }
    }
}

// ---------------------------------------------------------------------------
// Launch: QKV proj (tf32 mma, rounding epilogue) -> flash -> out proj
// ---------------------------------------------------------------------------
extern "C" void kernel_launch(void* const* d_in, const int* in_sizes, int n_in,
                              void* d_out, int out_size)
{
    const float* query = (const float*)d_in[0];   // [1,4096,512]
    const float* w_in  = (const float*)d_in[1];   // [1536,512]
    const float* b_in  = (const float*)d_in[2];   // [1536]
    const float* w_out = (const float*)d_in[3];   // [512,512]
    const float* b_out = (const float*)d_in[4];   // [512]
    float*       out   = (float*)d_out;           // [1,4096,512]

    float *qkv, *attn;
    cudaGetSymbolAddress((void**)&qkv,  g_qkv);
    cudaGetSymbolAddress((void**)&attn, g_attn);

    cudaFuncSetAttribute(gemm_tf32_bias,
                         cudaFuncAttributeMaxDynamicSharedMemorySize, GEMM_SMEM);
    cudaFuncSetAttribute(flash_mma_kernel,
                         cudaFuncAttributeMaxDynamicSharedMemorySize, FLASH_SMEM);

    // 1) QKV projection (+ Q pre-scale incl. log2e + tf32 rounding)
    {
        dim3 grid(LDQKV / 128, S_LEN / 128);   // (12, 32)
        gemm_tf32_bias<<<grid, 256, GEMM_SMEM>>>(query, w_in, b_in, qkv,
                                                 S_LEN, LDQKV, D_MODEL, 1);
    }

    // 2) Flash attention per head (8 warps, 16 rows/warp)
    {
        dim3 grid(S_LEN / 128, H_NUM);   // (32, 8) = 256 CTAs
        flash_mma_kernel<<<grid, 256, FLASH_SMEM>>>(qkv, attn);
    }

    // 3) Output projection (full fp32 output)
    {
        dim3 grid(D_MODEL / 128, S_LEN / 128);  // (4, 32)
        gemm_tf32_bias<<<grid, 256, GEMM_SMEM>>>(attn, w_out, b_out, out,
                                                 S_LEN, D_MODEL, D_MODEL, 0);
    }
}

// round 11
// speedup vs baseline: 1.2404x; 1.2404x over previous
#include <cuda_runtime.h>
#include <math_constants.h>
#include <cstdint>

// Problem constants
#define S_LEN   4096
#define D_MODEL 512
#define H_NUM   8
#define HD      64
#define LDQKV   1536      // 3*D_MODEL

// Q pre-scale: 1/sqrt(64) * log2(e)  (softmax runs in exp2 domain)
#define Q_PRESCALE 0.18033688011112042f

// Scratch (no cudaMalloc allowed)
__device__ float g_qkv[S_LEN * LDQKV];      // [4096,1536] Q|K|V (tf32, Q pre-scaled)
__device__ float g_attn[S_LEN * D_MODEL];   // [4096,512]  attention out (tf32-rounded)
__device__ float g_qr [S_LEN * D_MODEL];    // query, tf32-rounded
__device__ float g_wi [3 * D_MODEL * D_MODEL]; // in_proj_weight, tf32-rounded
__device__ float g_wo [D_MODEL * D_MODEL];  // out_proj_weight, tf32-rounded

// ---------------------------------------------------------------------------
// Helpers
// ---------------------------------------------------------------------------
__device__ __forceinline__ uint32_t f2tf32(float x) {
    uint32_t r;
    asm("cvt.rna.tf32.f32 %0, %1;" : "=r"(r) : "f"(x));
    return r;
}

__device__ __forceinline__ float ex2f(float x) {
    float y;
    asm("ex2.approx.ftz.f32 %0, %1;" : "=f"(y) : "f"(x));
    return y;
}

__device__ __forceinline__ void mma_tf32(float d[4], const uint32_t a[4],
                                         const uint32_t b[2], const float c[4]) {
    asm volatile(
        "mma.sync.aligned.m16n8k8.row.col.f32.tf32.tf32.f32 "
        "{%0,%1,%2,%3}, {%4,%5,%6,%7}, {%8,%9}, {%10,%11,%12,%13};"
        : "=f"(d[0]), "=f"(d[1]), "=f"(d[2]), "=f"(d[3])
        : "r"(a[0]), "r"(a[1]), "r"(a[2]), "r"(a[3]),
          "r"(b[0]), "r"(b[1]),
          "f"(c[0]), "f"(c[1]), "f"(c[2]), "f"(c[3]));
}

__device__ __forceinline__ uint32_t smem_u32(const void* p) {
    uint32_t a;
    asm("{ .reg .u64 t; cvta.to.shared.u64 t, %1; cvt.u32.u64 %0, t; }"
        : "=r"(a) : "l"(p));
    return a;
}

// cp.async.ca: 16B gmem->smem, L1-preserving (the .cg variant regressed in R4)
__device__ __forceinline__ void cp_async16(uint32_t dst, const void* src) {
    asm volatile("cp.async.ca.shared.global [%0], [%1], 16;"
                 :: "r"(dst), "l"(src));
}
#define CP_COMMIT()  asm volatile("cp.async.commit_group;")
#define CP_WAIT0()   asm volatile("cp.async.wait_group 0;")

// ---------------------------------------------------------------------------
// Elementwise tf32 rounding pass (src -> dst), float4 granular.
// ---------------------------------------------------------------------------
__global__ void round_tf32_kernel(const float* __restrict__ src,
                                  float* __restrict__ dst, int n4) {
    int i = blockIdx.x * blockDim.x + threadIdx.x;
    if (i < n4) {
        float4 v = *(const float4*)(src + 4 * i);
        v.x = __uint_as_float(f2tf32(v.x));
        v.y = __uint_as_float(f2tf32(v.y));
        v.z = __uint_as_float(f2tf32(v.z));
        v.w = __uint_as_float(f2tf32(v.w));
        *(float4*)(dst + 4 * i) = v;
    }
}

// ---------------------------------------------------------------------------
// tf32 tensor-core GEMM: C[M,N] = A[M,K] @ B[N,K]^T + bias[N]
// A and B are ALREADY tf32-valued; staging is raw cp.async.ca (no cvt, no
// register prefetch -> staging latency hidden behind the compute phase).
// qkv_round=1: epilogue scales Q columns (<512) by Q_PRESCALE + rounds all
// outputs to tf32 so the flash kernel stages with raw copies.
// ---------------------------------------------------------------------------
#define GLD 36
#define GEMM_SMEM (2 * 2 * 128 * GLD * 4)   // 73728 bytes

__global__ void __launch_bounds__(256, 2) gemm_tf32_bias(
    const float* __restrict__ A, const float* __restrict__ B,
    const float* __restrict__ bias, float* __restrict__ C,
    int M, int N, int K, int qkv_round)
{
    extern __shared__ float sm[];
    float* As[2] = { sm,                 sm + 128 * GLD     };
    float* Bs[2] = { sm + 2 * 128 * GLD, sm + 3 * 128 * GLD };

    const int tid  = threadIdx.x;
    const int lane = tid & 31;
    const int wid  = tid >> 5;
    const int qc   = lane & 3;
    const int qg   = lane >> 2;
    const int wm   = (wid & 3) * 32;
    const int wn   = (wid >> 2) * 64;
    const int m0   = blockIdx.y * 128;
    const int n0   = blockIdx.x * 128;

    // per-thread staging coordinates: 1024 float4 chunks per 128x32 tile
    const int srow = tid >> 1;                 // rows covered 2/step? no:
    // f = tid + i*256, row = f>>3 (0..127), c4 = (f&7)<<2 (0,4,..,28)
    uint32_t as_addr[2][4], bs_addr[2][4];
#pragma unroll
    for (int i = 0; i < 4; i++) {
        int f   = tid + i * 256;
        int row = f >> 3;
        int c4  = (f & 7) << 2;
        as_addr[0][i] = smem_u32(As[0] + row * GLD + c4);
        as_addr[1][i] = smem_u32(As[1] + row * GLD + c4);
        bs_addr[0][i] = smem_u32(Bs[0] + row * GLD + c4);
        bs_addr[1][i] = smem_u32(Bs[1] + row * GLD + c4);
    }

    float acc[2][8][4];
#pragma unroll
    for (int mf = 0; mf < 2; mf++)
#pragma unroll
        for (int nf = 0; nf < 8; nf++)
#pragma unroll
            for (int j = 0; j < 4; j++) acc[mf][nf][j] = 0.0f;

    const int nt = K / 32;

    // prologue: stage tile 0
#pragma unroll
    for (int i = 0; i < 4; i++) {
        int f   = tid + i * 256;
        int row = f >> 3;
        int c4  = (f & 7) << 2;
        cp_async16(as_addr[0][i], A + (size_t)(m0 + row) * K + c4);
        cp_async16(bs_addr[0][i], B + (size_t)(n0 + row) * K + c4);
    }
    CP_COMMIT();
    CP_WAIT0();
    __syncthreads();

    for (int t = 0; t < nt; t++) {
        const int cur = t & 1;
        // issue next tile into the other buffer (overlaps with compute below)
        if (t + 1 < nt) {
            const int nxt = cur ^ 1;
            int k0 = (t + 1) * 32;
#pragma unroll
            for (int i = 0; i < 4; i++) {
                int f   = tid + i * 256;
                int row = f >> 3;
                int c4  = (f & 7) << 2;
                cp_async16(as_addr[nxt][i], A + (size_t)(m0 + row) * K + k0 + c4);
                cp_async16(bs_addr[nxt][i], B + (size_t)(n0 + row) * K + k0 + c4);
            }
            CP_COMMIT();
        }

        // compute on current buffer
        const float* as = As[cur];
        const float* bs = Bs[cur];
#pragma unroll
        for (int kc = 0; kc < 4; kc++) {
            uint32_t bfr[8][2];
#pragma unroll
            for (int nf = 0; nf < 8; nf++) {
                const float* bp = bs + (wn + nf * 8 + qg) * GLD + kc * 8 + qc;
                bfr[nf][0] = __float_as_uint(bp[0]);
                bfr[nf][1] = __float_as_uint(bp[4]);
            }
#pragma unroll
            for (int mf = 0; mf < 2; mf++) {
                const float* ap = as + (wm + mf * 16 + qg) * GLD + kc * 8 + qc;
                uint32_t afr[4];
                afr[0] = __float_as_uint(ap[0]);
                afr[1] = __float_as_uint(ap[8 * GLD]);
                afr[2] = __float_as_uint(ap[4]);
                afr[3] = __float_as_uint(ap[8 * GLD + 4]);
#pragma unroll
                for (int nf = 0; nf < 8; nf++)
                    mma_tf32(acc[mf][nf], afr, bfr[nf], acc[mf][nf]);
            }
        }

        CP_WAIT0();        // next tile landed (issued before compute)
        __syncthreads();   // all warps done reading cur before it is reused
    }

    // epilogue: add bias, store
#pragma unroll
    for (int mf = 0; mf < 2; mf++) {
        int row0 = m0 + wm + mf * 16 + qg;
#pragma unroll
        for (int nf = 0; nf < 8; nf++) {
            int col = n0 + wn + nf * 8 + 2 * qc;
            float b0 = bias[col], b1 = bias[col + 1];
            float2 v0 = make_float2(acc[mf][nf][0] + b0, acc[mf][nf][1] + b1);
            float2 v1 = make_float2(acc[mf][nf][2] + b0, acc[mf][nf][3] + b1);
            if (qkv_round) {
                float sc = (col < D_MODEL) ? Q_PRESCALE : 1.0f;  // scale Q only
                v0.x = __uint_as_float(f2tf32(v0.x * sc));
                v0.y = __uint_as_float(f2tf32(v0.y * sc));
                v1.x = __uint_as_float(f2tf32(v1.x * sc));
                v1.y = __uint_as_float(f2tf32(v1.y * sc));
            }
            *(float2*)(C + (size_t)row0 * N + col)       = v0;
            *(float2*)(C + (size_t)(row0 + 8) * N + col) = v1;
        }
    }
}

// ---------------------------------------------------------------------------
// Flash attention (R5 structure verbatim -- best measured: flash ~264us).
// tf32 mma, Br=128 / Bc=64 / Hd=64, 4 warps, 32 q-rows/warp.
// kc-outer QK (K frags loaded once, shared across m-frags), kc-outer PV
// (V frags shared). Scalar LDS fragments. Two syncs per KV tile.
// Softmax in exp2 domain (log2e folded into Q pre-scale).
// Epilogue rounds attn to tf32 so the out-proj can cp.async raw.
// ---------------------------------------------------------------------------
#define LDA 68
#define LDB 72
#define FLASH_SMEM ((64 * LDA + 64 * LDB + 128 * LDA) * 4)   // 70656 B

__global__ void __launch_bounds__(128, 2) flash_mma_kernel(
    const float* __restrict__ qkv, float* __restrict__ attn_out)
{
    extern __shared__ float sm[];
    float* Ks = sm;                        // [64][LDA]
    float* Vs = sm + 64 * LDA;             // [64][LDB]
    float* Ps = sm + 64 * LDA + 64 * LDB;  // [128][LDA]  (Q staging, then P)

    const int tid  = threadIdx.x;
    const int lane = tid & 31;
    const int wid  = tid >> 5;
    const int qc   = lane & 3;
    const int qg   = lane >> 2;
    const int h    = blockIdx.y;
    const int q0   = blockIdx.x * 128;
    const int colb = h * HD;

    // ---- Stage Q tile (pre-scaled, pre-rounded): raw copy into Ps ----
#pragma unroll
    for (int i = 0; i < 16; i++) {
        int f   = tid + i * 128;
        int row = f >> 4;
        int c4  = (f & 15) << 2;
        *(float4*)(Ps + row * LDA + c4) =
            *(const float4*)(qkv + (size_t)(q0 + row) * LDQKV + colb + c4);
    }
    __syncthreads();

    // ---- Q fragments to registers: 2 m-frags x 8 k-chunks ----
    uint32_t qf[2][8][4];
#pragma unroll
    for (int mf = 0; mf < 2; mf++) {
        const int r0 = wid * 32 + mf * 16 + qg;
#pragma unroll
        for (int kc = 0; kc < 8; kc++) {
            int d0 = kc * 8;
            qf[mf][kc][0] = __float_as_uint(Ps[r0 * LDA + d0 + qc]);
            qf[mf][kc][1] = __float_as_uint(Ps[(r0 + 8) * LDA + d0 + qc]);
            qf[mf][kc][2] = __float_as_uint(Ps[r0 * LDA + d0 + qc + 4]);
            qf[mf][kc][3] = __float_as_uint(Ps[(r0 + 8) * LDA + d0 + qc + 4]);
        }
    }

    float o[2][8][4];
#pragma unroll
    for (int mf = 0; mf < 2; mf++)
#pragma unroll
        for (int nt = 0; nt < 8; nt++)
#pragma unroll
            for (int j = 0; j < 4; j++) o[mf][nt][j] = 0.0f;
    float m_run[2][2] = { {-CUDART_INF_F, -CUDART_INF_F},
                          {-CUDART_INF_F, -CUDART_INF_F} };
    float l_run[2][2] = { {0.f, 0.f}, {0.f, 0.f} };

    const int srow = tid >> 4;          // staging row 0..7 (stride 8)
    const int sc4  = (tid & 15) << 2;   // staging col 0..60

    for (int k0 = 0; k0 < S_LEN; k0 += 64) {
        __syncthreads();   // prev Ps/Ks/Vs reads done (covers Q-frag reads on t=0)
        // ---- Stage K, V tiles: raw LDG.128 -> STS.128 copy ----
        {
            const float* kbase = qkv + (size_t)(k0 + srow) * LDQKV + colb + D_MODEL + sc4;
#pragma unroll
            for (int r = 0; r < 8; r++) {
                *(float4*)(Ks + (srow + r * 8) * LDA + sc4) =
                    *(const float4*)(kbase + (size_t)(r * 8) * LDQKV);
                *(float4*)(Vs + (srow + r * 8) * LDB + sc4) =
                    *(const float4*)(kbase + (size_t)(r * 8) * LDQKV + D_MODEL);
            }
        }
        __syncthreads();

        // ---- S = Q K^T, kc-outer: K B-frags loaded once, shared by both mf ----
        float s[2][8][4];
#pragma unroll
        for (int mf = 0; mf < 2; mf++)
#pragma unroll
            for (int nt = 0; nt < 8; nt++)
#pragma unroll
                for (int j = 0; j < 4; j++) s[mf][nt][j] = 0.0f;

#pragma unroll
        for (int kc = 0; kc < 8; kc++) {
            uint32_t bfr[8][2];
#pragma unroll
            for (int nt = 0; nt < 8; nt++) {
                const float* kb = Ks + (nt * 8 + qg) * LDA + kc * 8 + qc;
                bfr[nt][0] = __float_as_uint(kb[0]);
                bfr[nt][1] = __float_as_uint(kb[4]);
            }
#pragma unroll
            for (int mf = 0; mf < 2; mf++)
#pragma unroll
                for (int nt = 0; nt < 8; nt++)
                    mma_tf32(s[mf][nt], qf[mf][kc], bfr[nt], s[mf][nt]);
        }

        // ---- Online softmax per m-fragment (exp2 domain), store P ----
#pragma unroll
        for (int mf = 0; mf < 2; mf++) {
            const int r0 = wid * 32 + mf * 16 + qg;
            const int r1 = r0 + 8;

            float mlo = -CUDART_INF_F, mhi = -CUDART_INF_F;
#pragma unroll
            for (int nt = 0; nt < 8; nt++) {
                mlo = fmaxf(mlo, fmaxf(s[mf][nt][0], s[mf][nt][1]));
                mhi = fmaxf(mhi, fmaxf(s[mf][nt][2], s[mf][nt][3]));
            }
            mlo = fmaxf(mlo, __shfl_xor_sync(0xffffffffu, mlo, 1));
            mlo = fmaxf(mlo, __shfl_xor_sync(0xffffffffu, mlo, 2));
            mhi = fmaxf(mhi, __shfl_xor_sync(0xffffffffu, mhi, 1));
            mhi = fmaxf(mhi, __shfl_xor_sync(0xffffffffu, mhi, 2));

            float mnlo = fmaxf(m_run[mf][0], mlo);
            float mnhi = fmaxf(m_run[mf][1], mhi);
            float alo  = ex2f(m_run[mf][0] - mnlo);   // 0 on first tile
            float ahi  = ex2f(m_run[mf][1] - mnhi);
            m_run[mf][0] = mnlo; m_run[mf][1] = mnhi;

            float tlo = 0.0f, thi = 0.0f;
#pragma unroll
            for (int nt = 0; nt < 8; nt++) {
                float p0 = ex2f(s[mf][nt][0] - mnlo);
                float p1 = ex2f(s[mf][nt][1] - mnlo);
                float p2 = ex2f(s[mf][nt][2] - mnhi);
                float p3 = ex2f(s[mf][nt][3] - mnhi);
                tlo += p0 + p1;
                thi += p2 + p3;
                uint2 plo = make_uint2(f2tf32(p0), f2tf32(p1));
                uint2 phi = make_uint2(f2tf32(p2), f2tf32(p3));
                *(uint2*)(Ps + r0 * LDA + nt * 8 + 2 * qc) = plo;
                *(uint2*)(Ps + r1 * LDA + nt * 8 + 2 * qc) = phi;
            }
            tlo += __shfl_xor_sync(0xffffffffu, tlo, 1);
            tlo += __shfl_xor_sync(0xffffffffu, tlo, 2);
            thi += __shfl_xor_sync(0xffffffffu, thi, 1);
            thi += __shfl_xor_sync(0xffffffffu, thi, 2);
            l_run[mf][0] = l_run[mf][0] * alo + tlo;
            l_run[mf][1] = l_run[mf][1] * ahi + thi;

#pragma unroll
            for (int nt = 0; nt < 8; nt++) {
                o[mf][nt][0] *= alo; o[mf][nt][1] *= alo;
                o[mf][nt][2] *= ahi; o[mf][nt][3] *= ahi;
            }
        }

        __syncwarp();   // P rows are warp-private; order STS before LDS

        // ---- O += P V  (kc-outer: V B-frags shared by both m-frags) ----
#pragma unroll
        for (int kc = 0; kc < 8; kc++) {
            uint32_t vfr[8][2];
#pragma unroll
            for (int nt = 0; nt < 8; nt++) {
                vfr[nt][0] = __float_as_uint(Vs[(kc * 8 + qc) * LDB + nt * 8 + qg]);
                vfr[nt][1] = __float_as_uint(Vs[(kc * 8 + qc + 4) * LDB + nt * 8 + qg]);
            }
#pragma unroll
            for (int mf = 0; mf < 2; mf++) {
                const int r0 = wid * 32 + mf * 16 + qg;
                const int r1 = r0 + 8;
                uint32_t a[4];
                a[0] = __float_as_uint(Ps[r0 * LDA + kc * 8 + qc]);
                a[1] = __float_as_uint(Ps[r1 * LDA + kc * 8 + qc]);
                a[2] = __float_as_uint(Ps[r0 * LDA + kc * 8 + qc + 4]);
                a[3] = __float_as_uint(Ps[r1 * LDA + kc * 8 + qc + 4]);
#pragma unroll
                for (int nt = 0; nt < 8; nt++)
                    mma_tf32(o[mf][nt], a, vfr[nt], o[mf][nt]);
            }
        }
    }

    // ---- Epilogue: normalize + round to tf32 (out-proj stages raw) ----
#pragma unroll
    for (int mf = 0; mf < 2; mf++) {
        const int r0 = wid * 32 + mf * 16 + qg;
        const int r1 = r0 + 8;
        float ilo = 1.0f / l_run[mf][0];
        float ihi = 1.0f / l_run[mf][1];
#pragma unroll
        for (int nt = 0; nt < 8; nt++) {
            uint2 vlo = make_uint2(f2tf32(o[mf][nt][0] * ilo), f2tf32(o[mf][nt][1] * ilo));
            uint2 vhi = make_uint2(f2tf32(o[mf][nt][2] * ihi), f2tf32(o[mf][nt][3] * ihi));
            *(uint2*)(attn_out + (size_t)(q0 + r0) * D_MODEL + colb + nt * 8 + 2 * qc) = vlo;
            *(uint2*)(attn_out + (size_t)(q0 + r1) * D_MODEL + colb + nt * 8 + 2 * qc) = vhi;
        }
    }
}

// ---------------------------------------------------------------------------
// Launch: pre-round -> QKV proj -> flash -> out proj
// ---------------------------------------------------------------------------
extern "C" void kernel_launch(void* const* d_in, const int* in_sizes, int n_in,
                              void* d_out, int out_size)
{
    const float* query = (const float*)d_in[0];   // [1,4096,512]
    const float* w_in  = (const float*)d_in[1];   // [1536,512]
    const float* b_in  = (const float*)d_in[2];   // [1536]
    const float* w_out = (const float*)d_in[3];   // [512,512]
    const float* b_out = (const float*)d_in[4];   // [512]
    float*       out   = (float*)d_out;           // [1,4096,512]

    float *qkv, *attn, *qr, *wi, *wo;
    cudaGetSymbolAddress((void**)&qkv,  g_qkv);
    cudaGetSymbolAddress((void**)&attn, g_attn);
    cudaGetSymbolAddress((void**)&qr,   g_qr);
    cudaGetSymbolAddress((void**)&wi,   g_wi);
    cudaGetSymbolAddress((void**)&wo,   g_wo);

    cudaFuncSetAttribute(gemm_tf32_bias,
                         cudaFuncAttributeMaxDynamicSharedMemorySize, GEMM_SMEM);
    cudaFuncSetAttribute(flash_mma_kernel,
                         cudaFuncAttributeMaxDynamicSharedMemorySize, FLASH_SMEM);

    // 0) Pre-round inputs to tf32 (idempotent rounding copies)
    {
        int nq = S_LEN * D_MODEL / 4;          // 524288
        int ni = 3 * D_MODEL * D_MODEL / 4;    // 196608
        int no = D_MODEL * D_MODEL / 4;        // 65536
        round_tf32_kernel<<<(nq + 255) / 256, 256>>>(query, qr, nq);
        round_tf32_kernel<<<(ni + 255) / 256, 256>>>(w_in,  wi, ni);
        round_tf32_kernel<<<(no + 255) / 256, 256>>>(w_out, wo, no);
    }

    // 1) QKV projection (+ Q pre-scale incl. log2e + tf32 rounding)
    {
        dim3 grid(LDQKV / 128, S_LEN / 128);   // (12, 32)
        gemm_tf32_bias<<<grid, 256, GEMM_SMEM>>>(qr, wi, b_in, qkv,
                                                 S_LEN, LDQKV, D_MODEL, 1);
    }

    // 2) Flash attention per head (R5 config)
    {
        dim3 grid(S_LEN / 128, H_NUM);   // (32, 8) = 256 CTAs
        flash_mma_kernel<<<grid, 128, FLASH_SMEM>>>(qkv, attn);
    }

    // 3) Output projection (full fp32 output)
    {
        dim3 grid(D_MODEL / 128, S_LEN / 128);  // (4, 32)
        gemm_tf32_bias<<<grid, 256, GEMM_SMEM>>>(attn, wo, b_out, out,
                                                 S_LEN, D_MODEL, D_MODEL, 0);
    }
}